// round 11
// baseline (speedup 1.0000x reference)
#include <cuda_runtime.h>
#include <cstdint>

#define K_DIM 4096
#define N_DIM 8192
#define INFCAP 100.0f
#define BP_EPS 1e-4f

// ---------------- scratch (no allocation; self-cleaning across graph replays) ----
__device__ float g_colsum[N_DIM];    // atomically accumulated; zeroed by prior-tail after use
__device__ float g_colsum2[N_DIM];   // atomically accumulated; zeroed by out-tail after use
__device__ float g_prior[N_DIM];     // overwritten every call
__device__ float g_tanh[N_DIM];      // overwritten every call
__device__ float g_dope[N_DIM];      // overwritten every call
__device__ float g_prod[K_DIM];      // overwritten every call
__device__ int   g_hxs_nonzero;      // set by k_colsum, reset by out-tail
__device__ unsigned g_cnt1;          // last-block counters (self-resetting)
__device__ unsigned g_cnt2;

__device__ __forceinline__ float tanh_approx(float x) {
    float r;
    asm("tanh.approx.f32 %0, %1;" : "=f"(r) : "f"(x));
    return r;
}

// ---------------- K1: column sum of Hxs + zero-detect, last block does prior ----
__global__ __launch_bounds__(256) void k_colsum(const float* __restrict__ M,
                                                const float* __restrict__ ps,
                                                const float* __restrict__ Min) {
    const int ROWS = 64;
    int tid = threadIdx.x;
    int cbase = blockIdx.x * 1024 + tid * 4;
    int r0 = blockIdx.y * ROWS;
    const float4* p = (const float4*)(M + (size_t)r0 * N_DIM + cbase);
    float4 a = make_float4(0.f, 0.f, 0.f, 0.f);
    bool nz = false;
#pragma unroll 8
    for (int r = 0; r < ROWS; r++) {
        float4 v = p[(size_t)r * (N_DIM / 4)];
        a.x += v.x; a.y += v.y; a.z += v.z; a.w += v.w;
        nz = nz || (v.x != 0.f) || (v.y != 0.f) || (v.z != 0.f) || (v.w != 0.f);
    }
    atomicAdd(&g_colsum[cbase + 0], a.x);
    atomicAdd(&g_colsum[cbase + 1], a.y);
    atomicAdd(&g_colsum[cbase + 2], a.z);
    atomicAdd(&g_colsum[cbase + 3], a.w);
    if (__syncthreads_or(nz) && tid == 0) atomicOr(&g_hxs_nonzero, 1);

    // ---- last-block-done: compute dope/phi/prior/tanh, reset g_colsum ----
    __shared__ bool last;
    __threadfence();
    __syncthreads();
    if (tid == 0) last = (atomicAdd(&g_cnt1, 1u) == 512u - 1u);
    __syncthreads();
    if (!last) return;

    for (int n = tid; n < N_DIM; n += 256) {
        float cs = __ldcg(&g_colsum[n]);   // atomics live in L2
        g_colsum[n] = 0.f;                 // self-clean for next replay
        float p0 = ps[2 * n], p1 = ps[2 * n + 1];
        float pn = __fdividef(p1, p0 + p1);
        float dope = __logf(1.f - pn) - __logf(pn);
        float m0 = Min[2 * n], m1 = Min[2 * n + 1];
        float mn = __fdividef(m1, m0 + m1);
        float phi = __logf(1.f - mn) - __logf(mn);
        g_dope[n] = dope;
        float pr = dope + phi + cs;
        pr = fminf(fmaxf(pr, -INFCAP), INFCAP);
        g_prior[n] = pr;
        g_tanh[n] = tanh_approx(0.5f * (pr + BP_EPS));  // == t_elem(1, pr, 0)
    }
    __syncthreads();
    if (tid == 0) g_cnt1 = 0u;
}

// ---------------- helpers ----------------
__device__ __forceinline__ float bp_elem(float t, float prod, float s) {
    if (t == 0.f) return 0.f;
    float y = s * __fdividef(prod, t);
    y = fminf(fmaxf(y, -1.f), 1.f);
    float r = __logf(__fdividef(1.f + y, 1.f - y));  // 2*atanh(y)
    return fminf(fmaxf(r, -1.f), 1.f);               // clip absorbs +-inf
}

__device__ __forceinline__ float t_elem(int h, float pr, float hx) {
    return tanh_approx(0.5f * (h ? (pr + BP_EPS - hx) : -hx));
}

// ---------------- K2a: per-row tanh product, 2 rows per CTA for MLP ----------------
// Fast path (Hxs all zero): row product = prod over {H=1} g_tanh[n], reads only H.
// Slow path: exact recompute streaming Hxs too.
__global__ __launch_bounds__(512) void k_prod(const float* __restrict__ Hxs,
                                              const int* __restrict__ H) {
    __shared__ float warp_prod[2][16];
    int k0 = blockIdx.x * 2;
    int tid = threadIdx.x;

    const int4* h4a = (const int4*)(H + (size_t)k0 * N_DIM);
    const int4* h4b = (const int4*)(H + (size_t)(k0 + 1) * N_DIM);

    float pa = 1.f, pb = 1.f;
    if (g_hxs_nonzero == 0) {
        const float4* th4 = (const float4*)g_tanh;
#pragma unroll
        for (int i = 0; i < 4; i++) {
            int idx = tid + i * 512;
            int4 ha = h4a[idx];
            int4 hb = h4b[idx];
            float4 t = th4[idx];
            pa *= (ha.x ? t.x : 1.f) * (ha.y ? t.y : 1.f)
                * (ha.z ? t.z : 1.f) * (ha.w ? t.w : 1.f);
            pb *= (hb.x ? t.x : 1.f) * (hb.y ? t.y : 1.f)
                * (hb.z ? t.z : 1.f) * (hb.w ? t.w : 1.f);
        }
    } else {
        const float4* hx4a = (const float4*)(Hxs + (size_t)k0 * N_DIM);
        const float4* hx4b = (const float4*)(Hxs + (size_t)(k0 + 1) * N_DIM);
        const float4* pr4 = (const float4*)g_prior;
#pragma unroll
        for (int i = 0; i < 4; i++) {
            int idx = tid + i * 512;
            float4 pr = pr4[idx];
            {
                float4 hx = hx4a[idx]; int4 h = h4a[idx];
                float tx = t_elem(h.x, pr.x, hx.x), ty = t_elem(h.y, pr.y, hx.y);
                float tz = t_elem(h.z, pr.z, hx.z), tw = t_elem(h.w, pr.w, hx.w);
                pa *= ((tx == 0.f) ? 1.f : tx) * ((ty == 0.f) ? 1.f : ty)
                    * ((tz == 0.f) ? 1.f : tz) * ((tw == 0.f) ? 1.f : tw);
            }
            {
                float4 hx = hx4b[idx]; int4 h = h4b[idx];
                float tx = t_elem(h.x, pr.x, hx.x), ty = t_elem(h.y, pr.y, hx.y);
                float tz = t_elem(h.z, pr.z, hx.z), tw = t_elem(h.w, pr.w, hx.w);
                pb *= ((tx == 0.f) ? 1.f : tx) * ((ty == 0.f) ? 1.f : ty)
                    * ((tz == 0.f) ? 1.f : tz) * ((tw == 0.f) ? 1.f : tw);
            }
        }
    }

#pragma unroll
    for (int off = 16; off; off >>= 1) {
        pa *= __shfl_xor_sync(0xffffffffu, pa, off);
        pb *= __shfl_xor_sync(0xffffffffu, pb, off);
    }
    if ((tid & 31) == 0) {
        warp_prod[0][tid >> 5] = pa;
        warp_prod[1][tid >> 5] = pb;
    }
    __syncthreads();
    if (tid < 32) {
        int which = tid >> 4;            // lanes 0-15 -> row a, 16-31 -> row b
        float q = warp_prod[which][tid & 15];
#pragma unroll
        for (int off = 8; off; off >>= 1) q *= __shfl_xor_sync(0xffffffffu, q, off, 16);
        if ((tid & 15) == 0) g_prod[k0 + which] = q;
    }
}

// ---------------- K2b: output writer (pure zero-write on fast path) ----------------
__global__ __launch_bounds__(512) void k_write(const float* __restrict__ Hxs,
                                               const int* __restrict__ H,
                                               const int* __restrict__ x,
                                               float* __restrict__ out_Hxs) {
    int k = blockIdx.x;
    int tid = threadIdx.x;
    float prod = g_prod[k];
    float4* o4 = (float4*)(out_Hxs + (size_t)k * N_DIM);

    if (prod == 0.f) {
        float4 z = make_float4(0.f, 0.f, 0.f, 0.f);
#pragma unroll
        for (int i = 0; i < 4; i++) o4[tid + i * 512] = z;
    } else {
        const float4* hx4 = (const float4*)(Hxs + (size_t)k * N_DIM);
        const int4*   h4  = (const int4*)(H + (size_t)k * N_DIM);
        const float4* pr4 = (const float4*)g_prior;
        bool hxz = (g_hxs_nonzero == 0);
        float s = (float)(1 - 2 * x[k]);
#pragma unroll
        for (int i = 0; i < 4; i++) {
            int idx = tid + i * 512;
            float4 hx = hxz ? make_float4(0.f, 0.f, 0.f, 0.f) : hx4[idx];
            int4   h  = h4[idx];
            float4 pr = pr4[idx];
            float4 o;
            o.x = bp_elem(t_elem(h.x, pr.x, hx.x), prod, s);
            o.y = bp_elem(t_elem(h.y, pr.y, hx.y), prod, s);
            o.z = bp_elem(t_elem(h.z, pr.z, hx.z), prod, s);
            o.w = bp_elem(t_elem(h.w, pr.w, hx.w), prod, s);
            o4[idx] = o;
        }
    }
}

// ---------------- K3: colsum of Hxs_new (skip zero rows), last block does M_out ----
__global__ __launch_bounds__(256) void k_colsum2(const float* __restrict__ M,
                                                 float* __restrict__ out_M) {
    const int ROWS = 64;
    int tid = threadIdx.x;
    int cbase = blockIdx.x * 1024 + tid * 4;
    int r0 = blockIdx.y * ROWS;
    const float4* p = (const float4*)(M + (size_t)r0 * N_DIM + cbase);
    float4 a = make_float4(0.f, 0.f, 0.f, 0.f);
    bool any = false;
    for (int r = 0; r < ROWS; r++) {
        if (g_prod[r0 + r] != 0.f) {      // zero-product rows are exactly 0: skip
            any = true;
            float4 v = p[(size_t)r * (N_DIM / 4)];
            a.x += v.x; a.y += v.y; a.z += v.z; a.w += v.w;
        }
    }
    if (any) {
        atomicAdd(&g_colsum2[cbase + 0], a.x);
        atomicAdd(&g_colsum2[cbase + 1], a.y);
        atomicAdd(&g_colsum2[cbase + 2], a.z);
        atomicAdd(&g_colsum2[cbase + 3], a.w);
    }

    // ---- last-block-done: output beliefs, reset scratch ----
    __shared__ bool last;
    __threadfence();
    __syncthreads();
    if (tid == 0) last = (atomicAdd(&g_cnt2, 1u) == 512u - 1u);
    __syncthreads();
    if (!last) return;

    for (int n = tid; n < N_DIM; n += 256) {
        float cs2 = __ldcg(&g_colsum2[n]);
        g_colsum2[n] = 0.f;               // self-clean for next replay
        float z = (1.f - tanhf((cs2 + g_dope[n]) * 0.5f)) * 0.5f;
        out_M[2 * n + 0] = 1.f - z;
        out_M[2 * n + 1] = z;
    }
    __syncthreads();
    if (tid == 0) { g_cnt2 = 0u; g_hxs_nonzero = 0; }
}

extern "C" void kernel_launch(void* const* d_in, const int* in_sizes, int n_in,
                              void* d_out, int out_size) {
    const float* ps  = (const float*)d_in[0];
    const float* Min = (const float*)d_in[1];
    const float* Hxs = (const float*)d_in[2];
    const int*   x   = (const int*)d_in[3];
    const int*   H   = (const int*)d_in[4];

    float* out     = (float*)d_out;
    float* out_M   = out;                 // M_out [N,2] first
    float* out_Hxs = out + 2 * N_DIM;     // Hxs_new [K,N] second

    k_colsum <<<dim3(N_DIM / 1024, K_DIM / 64), 256>>>(Hxs, ps, Min);
    k_prod   <<<K_DIM / 2, 512>>>(Hxs, H);
    k_write  <<<K_DIM, 512>>>(Hxs, H, x, out_Hxs);
    k_colsum2<<<dim3(N_DIM / 1024, K_DIM / 64), 256>>>(out_Hxs, out_M);
}

// round 14
// speedup vs baseline: 1.2482x; 1.2482x over previous
#include <cuda_runtime.h>
#include <cstdint>

#define K_DIM 4096
#define N_DIM 8192
#define INFCAP 100.0f
#define BP_EPS 1e-4f
#define STRIPES 64   // K_DIM / 64 row-stripes for partial sums

// ---------------- scratch (no allocation; everything overwritten each call) ----
// g_part is SHARED between the two colsum phases (disjoint lifetimes):
//   phase 1: k_colsum writes, k_prior reads.  phase 2: k_colsum2 writes, k_out reads.
__device__ float g_part[STRIPES * N_DIM];   // 2 MB, L2-resident
__device__ float g_prior[N_DIM];
__device__ float g_tanh[N_DIM];             // tanh(0.5*(prior+EPS)) fast-path factor
__device__ float g_dope[N_DIM];
__device__ float g_prod[K_DIM];             // per-row tanh product
__device__ int   g_nzflags[8 * STRIPES];    // per-block Hxs!=0 flags (unconditional)
__device__ int   g_hxs_nz;                  // reduced flag (written by k_prior blk 0)

__device__ __forceinline__ float tanh_approx(float x) {
    float r;
    asm("tanh.approx.f32 %0, %1;" : "=f"(r) : "f"(x));
    return r;
}

// ---------------- K1: column partial sums of Hxs + zero-detect ----------------
// grid (8, 64), block 256. Block (bx,by): 1024 cols x 64 rows -> partial slab.
__global__ __launch_bounds__(256) void k_colsum(const float* __restrict__ M) {
    const int ROWS = 64;
    int tid = threadIdx.x;
    int cbase = blockIdx.x * 1024 + tid * 4;
    int r0 = blockIdx.y * ROWS;
    const float4* p = (const float4*)(M + (size_t)r0 * N_DIM + cbase);
    float4 a = make_float4(0.f, 0.f, 0.f, 0.f);
    bool nz = false;
#pragma unroll 8
    for (int r = 0; r < ROWS; r++) {
        float4 v = p[(size_t)r * (N_DIM / 4)];
        a.x += v.x; a.y += v.y; a.z += v.z; a.w += v.w;
        nz = nz || (v.x != 0.f) || (v.y != 0.f) || (v.z != 0.f) || (v.w != 0.f);
    }
    *(float4*)&g_part[(size_t)blockIdx.y * N_DIM + cbase] = a;
    bool bnz = __syncthreads_or(nz);
    if (tid == 0) g_nzflags[blockIdx.y * 8 + blockIdx.x] = bnz ? 1 : 0;  // unconditional
}

// ---------------- K1b: reduce partials -> dope/phi/prior/tanh; reduce nz flag ----
__global__ __launch_bounds__(256) void k_prior(const float* __restrict__ ps,
                                               const float* __restrict__ Min) {
    int n = blockIdx.x * blockDim.x + threadIdx.x;
    if (n < N_DIM) {
        float cs = 0.f;
#pragma unroll 8
        for (int j = 0; j < STRIPES; j++) cs += g_part[(size_t)j * N_DIM + n];
        float p0 = ps[2 * n], p1 = ps[2 * n + 1];
        float pn = p1 / (p0 + p1);
        float dope = logf(1.f - pn) - logf(pn);
        float m0 = Min[2 * n], m1 = Min[2 * n + 1];
        float mn = m1 / (m0 + m1);
        float phi = logf(1.f - mn) - logf(mn);
        g_dope[n] = dope;
        float pr = dope + phi + cs;
        pr = fminf(fmaxf(pr, -INFCAP), INFCAP);
        g_prior[n] = pr;
        g_tanh[n] = tanh_approx(0.5f * (pr + BP_EPS));  // == t_elem(1, pr, 0)
    }
    // block 0 reduces the 512 nz flags (unconditional write -> no reset needed)
    if (blockIdx.x == 0) {
        int f = g_nzflags[threadIdx.x * 2] | g_nzflags[threadIdx.x * 2 + 1];
        bool any = __syncthreads_or(f != 0);
        if (threadIdx.x == 0) g_hxs_nz = any ? 1 : 0;
    }
}

// ---------------- helpers ----------------
__device__ __forceinline__ float bp_elem(float t, float prod, float s) {
    if (t == 0.f) return 0.f;
    float y = s * __fdividef(prod, t);
    y = fminf(fmaxf(y, -1.f), 1.f);
    float r = __logf(__fdividef(1.f + y, 1.f - y));  // 2*atanh(y)
    return fminf(fmaxf(r, -1.f), 1.f);               // clip absorbs +-inf
}

__device__ __forceinline__ float t_elem(int h, float pr, float hx) {
    return tanh_approx(0.5f * (h ? (pr + BP_EPS - hx) : -hx));
}

// ---------------- K2a: per-row tanh product, 2 rows per CTA for MLP ----------------
// Fast path (Hxs all zero): row product = prod over {H=1} g_tanh[n]; reads only H.
// Slow path (general inputs): exact recompute streaming Hxs too.
__global__ __launch_bounds__(512) void k_prod(const float* __restrict__ Hxs,
                                              const int* __restrict__ H) {
    __shared__ float warp_prod[2][16];
    int k0 = blockIdx.x * 2;
    int tid = threadIdx.x;

    const int4* h4a = (const int4*)(H + (size_t)k0 * N_DIM);
    const int4* h4b = (const int4*)(H + (size_t)(k0 + 1) * N_DIM);

    float pa = 1.f, pb = 1.f;
    if (g_hxs_nz == 0) {
        const float4* th4 = (const float4*)g_tanh;
#pragma unroll
        for (int i = 0; i < 4; i++) {
            int idx = tid + i * 512;
            int4 ha = h4a[idx];
            int4 hb = h4b[idx];
            float4 t = th4[idx];
            pa *= (ha.x ? t.x : 1.f) * (ha.y ? t.y : 1.f)
                * (ha.z ? t.z : 1.f) * (ha.w ? t.w : 1.f);
            pb *= (hb.x ? t.x : 1.f) * (hb.y ? t.y : 1.f)
                * (hb.z ? t.z : 1.f) * (hb.w ? t.w : 1.f);
        }
    } else {
        const float4* hx4a = (const float4*)(Hxs + (size_t)k0 * N_DIM);
        const float4* hx4b = (const float4*)(Hxs + (size_t)(k0 + 1) * N_DIM);
        const float4* pr4 = (const float4*)g_prior;
#pragma unroll
        for (int i = 0; i < 4; i++) {
            int idx = tid + i * 512;
            float4 pr = pr4[idx];
            {
                float4 hx = hx4a[idx]; int4 h = h4a[idx];
                float tx = t_elem(h.x, pr.x, hx.x), ty = t_elem(h.y, pr.y, hx.y);
                float tz = t_elem(h.z, pr.z, hx.z), tw = t_elem(h.w, pr.w, hx.w);
                pa *= ((tx == 0.f) ? 1.f : tx) * ((ty == 0.f) ? 1.f : ty)
                    * ((tz == 0.f) ? 1.f : tz) * ((tw == 0.f) ? 1.f : tw);
            }
            {
                float4 hx = hx4b[idx]; int4 h = h4b[idx];
                float tx = t_elem(h.x, pr.x, hx.x), ty = t_elem(h.y, pr.y, hx.y);
                float tz = t_elem(h.z, pr.z, hx.z), tw = t_elem(h.w, pr.w, hx.w);
                pb *= ((tx == 0.f) ? 1.f : tx) * ((ty == 0.f) ? 1.f : ty)
                    * ((tz == 0.f) ? 1.f : tz) * ((tw == 0.f) ? 1.f : tw);
            }
        }
    }

#pragma unroll
    for (int off = 16; off; off >>= 1) {
        pa *= __shfl_xor_sync(0xffffffffu, pa, off);
        pb *= __shfl_xor_sync(0xffffffffu, pb, off);
    }
    if ((tid & 31) == 0) {
        warp_prod[0][tid >> 5] = pa;
        warp_prod[1][tid >> 5] = pb;
    }
    __syncthreads();
    if (tid < 32) {
        int which = tid >> 4;            // lanes 0-15 -> row a, 16-31 -> row b
        float q = warp_prod[which][tid & 15];
#pragma unroll
        for (int off = 8; off; off >>= 1) q *= __shfl_xor_sync(0xffffffffu, q, off, 16);
        if ((tid & 15) == 0) g_prod[k0 + which] = q;
    }
}

// ---------------- K2b: output writer (pure zero-write on fast path) ----------------
__global__ __launch_bounds__(512) void k_write(const float* __restrict__ Hxs,
                                               const int* __restrict__ H,
                                               const int* __restrict__ x,
                                               float* __restrict__ out_Hxs) {
    int k = blockIdx.x;
    int tid = threadIdx.x;
    float prod = g_prod[k];
    float4* o4 = (float4*)(out_Hxs + (size_t)k * N_DIM);

    if (prod == 0.f) {
        float4 z = make_float4(0.f, 0.f, 0.f, 0.f);
#pragma unroll
        for (int i = 0; i < 4; i++) o4[tid + i * 512] = z;
    } else {
        const float4* hx4 = (const float4*)(Hxs + (size_t)k * N_DIM);
        const int4*   h4  = (const int4*)(H + (size_t)k * N_DIM);
        const float4* pr4 = (const float4*)g_prior;
        bool hxz = (g_hxs_nz == 0);
        float s = (float)(1 - 2 * x[k]);
#pragma unroll
        for (int i = 0; i < 4; i++) {
            int idx = tid + i * 512;
            float4 hx = hxz ? make_float4(0.f, 0.f, 0.f, 0.f) : hx4[idx];
            int4   h  = h4[idx];
            float4 pr = pr4[idx];
            float4 o;
            o.x = bp_elem(t_elem(h.x, pr.x, hx.x), prod, s);
            o.y = bp_elem(t_elem(h.y, pr.y, hx.y), prod, s);
            o.z = bp_elem(t_elem(h.z, pr.z, hx.z), prod, s);
            o.w = bp_elem(t_elem(h.w, pr.w, hx.w), prod, s);
            o4[idx] = o;
        }
    }
}

// ---------------- K3: column partial sums of Hxs_new, skipping zero rows ----------
// Reuses g_part (phase-1 consumers already done). Writes partials
// unconditionally (zeros when all rows skipped) -> no reset needed.
__global__ __launch_bounds__(256) void k_colsum2(const float* __restrict__ M) {
    const int ROWS = 64;
    int tid = threadIdx.x;
    int cbase = blockIdx.x * 1024 + tid * 4;
    int r0 = blockIdx.y * ROWS;
    const float4* p = (const float4*)(M + (size_t)r0 * N_DIM + cbase);
    float4 a = make_float4(0.f, 0.f, 0.f, 0.f);
    for (int r = 0; r < ROWS; r++) {
        if (g_prod[r0 + r] != 0.f) {      // zero-product rows are exactly 0: skip
            float4 v = p[(size_t)r * (N_DIM / 4)];
            a.x += v.x; a.y += v.y; a.z += v.z; a.w += v.w;
        }
    }
    *(float4*)&g_part[(size_t)blockIdx.y * N_DIM + cbase] = a;
}

// ---------------- K4: reduce partials -> output beliefs ----------------
__global__ __launch_bounds__(256) void k_out(float* __restrict__ out_M) {
    int n = blockIdx.x * blockDim.x + threadIdx.x;
    if (n >= N_DIM) return;
    float cs2 = 0.f;
#pragma unroll 8
    for (int j = 0; j < STRIPES; j++) cs2 += g_part[(size_t)j * N_DIM + n];
    float z = (1.f - tanhf((cs2 + g_dope[n]) * 0.5f)) * 0.5f;
    out_M[2 * n + 0] = 1.f - z;
    out_M[2 * n + 1] = z;
}

extern "C" void kernel_launch(void* const* d_in, const int* in_sizes, int n_in,
                              void* d_out, int out_size) {
    const float* ps  = (const float*)d_in[0];
    const float* Min = (const float*)d_in[1];
    const float* Hxs = (const float*)d_in[2];
    const int*   x   = (const int*)d_in[3];
    const int*   H   = (const int*)d_in[4];

    float* out     = (float*)d_out;
    float* out_M   = out;                 // M_out [N,2] first
    float* out_Hxs = out + 2 * N_DIM;     // Hxs_new [K,N] second

    k_colsum <<<dim3(N_DIM / 1024, STRIPES), 256>>>(Hxs);
    k_prior  <<<N_DIM / 256, 256>>>(ps, Min);
    k_prod   <<<K_DIM / 2, 512>>>(Hxs, H);
    k_write  <<<K_DIM, 512>>>(Hxs, H, x, out_Hxs);
    k_colsum2<<<dim3(N_DIM / 1024, STRIPES), 256>>>(out_Hxs);
    k_out    <<<N_DIM / 256, 256>>>(out_M);
}